// round 8
// baseline (speedup 1.0000x reference)
#include <cuda_runtime.h>
#include <cuda_fp16.h>
#include <cstdint>

#define BATCH 1024
#define SEQ   256
#define CDIM  512
#define HEAD  64
#define MROWS (BATCH * SEQ)
#define LOG2E 1.4426950408889634f

// Scratch: Q (pre-scaled by 0.125*log2e), K, V stored as tf32 bit patterns.
__device__ uint32_t g_Q[(size_t)MROWS * HEAD];
__device__ uint32_t g_K[(size_t)MROWS * HEAD];
__device__ uint32_t g_V[(size_t)MROWS * HEAD];
// Pre-transposed W as tf32: [N=192][K=512].
__device__ uint32_t g_Wt[192 * 512];

// ---------------------------------------------------------------------------
// helpers (legacy pipe — tcgen05 unavailable in this build path)
// ---------------------------------------------------------------------------
__device__ __forceinline__ uint32_t f2tf32(float x) {
    uint32_t r;
    asm("cvt.rna.tf32.f32 %0, %1;" : "=r"(r) : "f"(x));
    return r;
}
__device__ __forceinline__ void mma_tf32(float d[4], const uint32_t a[4], const uint32_t b[2]) {
    asm volatile(
        "mma.sync.aligned.m16n8k8.row.col.f32.tf32.tf32.f32 "
        "{%0,%1,%2,%3}, {%4,%5,%6,%7}, {%8,%9}, {%0,%1,%2,%3};"
        : "+f"(d[0]), "+f"(d[1]), "+f"(d[2]), "+f"(d[3])
        : "r"(a[0]), "r"(a[1]), "r"(a[2]), "r"(a[3]), "r"(b[0]), "r"(b[1]));
}
__device__ __forceinline__ uint32_t smem_u32(const void* p) {
    uint32_t a;
    asm("{ .reg .u64 t; cvta.to.shared.u64 t, %1; cvt.u32.u64 %0, t; }" : "=r"(a) : "l"(p));
    return a;
}

// ---------------------------------------------------------------------------
// Prep: convert + transpose W into [192][512] tf32
// ---------------------------------------------------------------------------
__global__ void wcvt_kernel(const float* __restrict__ Wq, const float* __restrict__ Wk,
                            const float* __restrict__ Wv) {
    int i = blockIdx.x * 256 + threadIdx.x;
    if (i >= 192 * 512) return;
    int n = i >> 9, k = i & 511;
    const float* W = (n < 64) ? Wq : ((n < 128) ? Wk : Wv);
    g_Wt[i] = f2tf32(W[k * HEAD + (n & 63)]);
}

// ---------------------------------------------------------------------------
// Kernel 1: QKV projection, single-pass tf32 m16n8k8 (MAC-count halved vs
// 2-term fp16 split). Block tile 128(M) x 192(N), BK=32, double-buffered.
// 512 threads: 16 warps = 4M x 4N, warp tile 32x48.
// smem word-stride 36 -> all fragment LDS conflict-free.
// ---------------------------------------------------------------------------
#define A_OFF    0
#define B_OFF    18432
#define STAGE_B  46080
#define QKV_SMEM (2 * STAGE_B)   // 92160

__device__ __forceinline__ void qkv_ldg_a(const float* __restrict__ x, int row0,
                                          const int a_r[2], int a_q, int kc, float4 av[2]) {
#pragma unroll
    for (int i = 0; i < 2; i++)
        av[i] = *reinterpret_cast<const float4*>(
            &x[(size_t)(row0 + a_r[i]) * CDIM + kc + a_q * 4]);
}

__device__ __forceinline__ void qkv_cvt_a(char* stage, const int a_r[2], int a_q,
                                          const float4 av[2]) {
#pragma unroll
    for (int i = 0; i < 2; i++) {
        float4 v = av[i];
        *reinterpret_cast<uint4*>(stage + A_OFF + a_r[i] * 144 + a_q * 16) =
            make_uint4(f2tf32(v.x), f2tf32(v.y), f2tf32(v.z), f2tf32(v.w));
    }
}

__device__ __forceinline__ void qkv_cp_b(char* stage, int tid, int kc) {
    // B tile: 192 rows x 32 tf32 cols = 1536 x 16B; 512 threads x 3.
#pragma unroll
    for (int s3 = 0; s3 < 3; s3++) {
        int ui = s3 * 512 + tid;
        int n = ui >> 3, ch = ui & 7;
        uint32_t dst;
        asm("{ .reg .u64 t; cvta.to.shared.u64 t, %1; cvt.u32.u64 %0, t; }"
            : "=r"(dst) : "l"(stage + B_OFF + n * 144 + ch * 16));
        asm volatile("cp.async.ca.shared.global [%0], [%1], 16;"
                     :: "r"(dst), "l"(g_Wt + n * 512 + kc + ch * 4));
    }
}

__global__ void __launch_bounds__(512, 1)
qkv_proj_kernel(const float* __restrict__ x) {
    extern __shared__ char smem[];
    const int tid    = threadIdx.x;
    const int lane   = tid & 31;
    const int wid    = tid >> 5;
    const int warp_m = wid & 3;    // 0..3 -> M rows (x32)
    const int warp_n = wid >> 2;   // 0..3 -> N cols (x48)
    const int gid    = lane >> 2;
    const int tig    = lane & 3;
    const int row0   = blockIdx.x * 128;

    float acc[2][6][4];
#pragma unroll
    for (int mt = 0; mt < 2; mt++)
#pragma unroll
        for (int nt = 0; nt < 6; nt++)
#pragma unroll
            for (int i = 0; i < 4; i++) acc[mt][nt][i] = 0.f;

    float4 av[2];
    const int a_r[2] = {tid >> 3, (512 + tid) >> 3};
    const int a_q = tid & 7;

    // ---- prologue ----
    qkv_cp_b(smem, tid, 0);
    asm volatile("cp.async.commit_group;" ::: "memory");
    qkv_ldg_a(x, row0, a_r, a_q, 0, av);
    qkv_cvt_a(smem, a_r, a_q, av);

    for (int c = 0; c < 16; c++) {
        const int cur = (c & 1) * STAGE_B;
        asm volatile("cp.async.wait_group 0;" ::: "memory");
        __syncthreads();

        if (c + 1 < 16) {
            const int nxt = ((c + 1) & 1) * STAGE_B;
            const int kc = (c + 1) * 32;
            qkv_ldg_a(x, row0, a_r, a_q, kc, av);   // long-latency, used after MMAs
            qkv_cp_b(smem + nxt, tid, kc);
            asm volatile("cp.async.commit_group;" ::: "memory");
        }

        // ---- MMAs for chunk c ----
        const uint32_t* A = reinterpret_cast<const uint32_t*>(smem + cur + A_OFF);
        const uint32_t* B = reinterpret_cast<const uint32_t*>(smem + cur + B_OFF);
#pragma unroll
        for (int ks = 0; ks < 4; ks++) {
            const int kw = ks * 8 + tig;
            uint32_t ah[2][4];
#pragma unroll
            for (int mt = 0; mt < 2; mt++) {
                int r = warp_m * 32 + mt * 16 + gid;
                ah[mt][0] = A[r * 36 + kw];
                ah[mt][1] = A[(r + 8) * 36 + kw];
                ah[mt][2] = A[r * 36 + kw + 4];
                ah[mt][3] = A[(r + 8) * 36 + kw + 4];
            }
#pragma unroll
            for (int nt = 0; nt < 6; nt++) {
                int n = warp_n * 48 + nt * 8 + gid;
                uint32_t bb[2];
                bb[0] = B[n * 36 + kw];
                bb[1] = B[n * 36 + kw + 4];
                mma_tf32(acc[0][nt], ah[0], bb);
                mma_tf32(acc[1][nt], ah[1], bb);
            }
        }

        // ---- convert A(c+1) into next stage (off critical path) ----
        if (c + 1 < 16)
            qkv_cvt_a(smem + ((c + 1) & 1) * STAGE_B, a_r, a_q, av);
    }

    // ---- writeback as tf32 bit patterns; Q pre-scaled by 0.125*log2e ----
    const float qs = 0.125f * LOG2E;
#pragma unroll
    for (int mt = 0; mt < 2; mt++) {
        int r = row0 + warp_m * 32 + mt * 16 + gid;
#pragma unroll
        for (int nt = 0; nt < 6; nt++) {
            int n = warp_n * 48 + nt * 8 + tig * 2;
            uint32_t* dst = (n < 64) ? g_Q : ((n < 128) ? g_K : g_V);
            float s = (n < 64) ? qs : 1.0f;
            int h = n & 63;
            *reinterpret_cast<uint2*>(&dst[(size_t)r * HEAD + h]) =
                make_uint2(f2tf32(acc[mt][nt][0] * s), f2tf32(acc[mt][nt][1] * s));
            *reinterpret_cast<uint2*>(&dst[(size_t)(r + 8) * HEAD + h]) =
                make_uint2(f2tf32(acc[mt][nt][2] * s), f2tf32(acc[mt][nt][3] * s));
        }
    }
}

// ---------------------------------------------------------------------------
// Kernel 2: causal flash attention. Scores are in log2 domain (Q pre-scaled
// by 0.125*log2e), so softmax uses exp2f (one MUFU, no FMUL). Heavy tiles
// first; launch_bounds(128,4).
// ---------------------------------------------------------------------------
__global__ void __launch_bounds__(128, 4)
attn_kernel(float* __restrict__ out) {
    __shared__ uint32_t KPs[64][68];
    __shared__ uint32_t Vs[64][72];

    const int b = blockIdx.y;
    const int qt = (gridDim.x - 1) - blockIdx.x;  // heavy (qt=3) blocks launch first
    const int tid = threadIdx.x;
    const int lane = tid & 31;
    const int w = tid >> 5;
    const int gid = lane >> 2;
    const int tig = lane & 3;

    uint32_t qf[8][4];
    {
        const size_t qbase = ((size_t)b * SEQ + (size_t)qt * 64 + w * 16) * HEAD;
#pragma unroll
        for (int kk = 0; kk < 8; kk++) {
            int k = kk * 8 + tig;
            qf[kk][0] = g_Q[qbase + gid * HEAD + k];
            qf[kk][1] = g_Q[qbase + (gid + 8) * HEAD + k];
            qf[kk][2] = g_Q[qbase + gid * HEAD + k + 4];
            qf[kk][3] = g_Q[qbase + (gid + 8) * HEAD + k + 4];
        }
    }

    float m0 = -1e30f, m1 = -1e30f, l0 = 0.f, l1 = 0.f;
    float o[8][4];
#pragma unroll
    for (int nt = 0; nt < 8; nt++)
#pragma unroll
        for (int i = 0; i < 4; i++) o[nt][i] = 0.f;

    for (int j = 0; j <= qt; j++) {
        __syncthreads();
        const size_t kvb = ((size_t)b * SEQ + (size_t)j * 64) * HEAD;
#pragma unroll
        for (int s = 0; s < 8; s++) {
            int idx4 = s * 128 + tid;
            int key = idx4 >> 4;
            int h = (idx4 & 15) * 4;
            *reinterpret_cast<uint4*>(&KPs[key][h]) =
                *reinterpret_cast<const uint4*>(&g_K[kvb + (size_t)key * HEAD + h]);
            *reinterpret_cast<uint4*>(&Vs[key][h]) =
                *reinterpret_cast<const uint4*>(&g_V[kvb + (size_t)key * HEAD + h]);
        }
        __syncthreads();

        float sc[8][4];
#pragma unroll
        for (int nt = 0; nt < 8; nt++)
#pragma unroll
            for (int i = 0; i < 4; i++) sc[nt][i] = 0.f;

#pragma unroll
        for (int kk = 0; kk < 8; kk++) {
            int k = kk * 8 + tig;
#pragma unroll
            for (int nt = 0; nt < 8; nt++) {
                uint32_t bf[2];
                bf[0] = KPs[nt * 8 + gid][k];
                bf[1] = KPs[nt * 8 + gid][k + 4];
                mma_tf32(sc[nt], qf[kk], bf);
            }
        }

        if (j == qt) {
            int q0 = w * 16 + gid, q1 = q0 + 8;
#pragma unroll
            for (int nt = 0; nt < 8; nt++) {
                int kc = nt * 8 + tig * 2;
                if (kc > q0) sc[nt][0] = -1e30f;
                if (kc + 1 > q0) sc[nt][1] = -1e30f;
                if (kc > q1) sc[nt][2] = -1e30f;
                if (kc + 1 > q1) sc[nt][3] = -1e30f;
            }
        }

        float rm0 = -1e30f, rm1 = -1e30f;
#pragma unroll
        for (int nt = 0; nt < 8; nt++) {
            rm0 = fmaxf(rm0, fmaxf(sc[nt][0], sc[nt][1]));
            rm1 = fmaxf(rm1, fmaxf(sc[nt][2], sc[nt][3]));
        }
        rm0 = fmaxf(rm0, __shfl_xor_sync(0xffffffffu, rm0, 1));
        rm0 = fmaxf(rm0, __shfl_xor_sync(0xffffffffu, rm0, 2));
        rm1 = fmaxf(rm1, __shfl_xor_sync(0xffffffffu, rm1, 1));
        rm1 = fmaxf(rm1, __shfl_xor_sync(0xffffffffu, rm1, 2));

        float mn0 = fmaxf(m0, rm0), mn1 = fmaxf(m1, rm1);
        float a0 = exp2f(m0 - mn0), a1 = exp2f(m1 - mn1);

        float rs0 = 0.f, rs1 = 0.f;
#pragma unroll
        for (int nt = 0; nt < 8; nt++) {
            sc[nt][0] = exp2f(sc[nt][0] - mn0);
            sc[nt][1] = exp2f(sc[nt][1] - mn0);
            sc[nt][2] = exp2f(sc[nt][2] - mn1);
            sc[nt][3] = exp2f(sc[nt][3] - mn1);
            rs0 += sc[nt][0] + sc[nt][1];
            rs1 += sc[nt][2] + sc[nt][3];
        }
        rs0 += __shfl_xor_sync(0xffffffffu, rs0, 1);
        rs0 += __shfl_xor_sync(0xffffffffu, rs0, 2);
        rs1 += __shfl_xor_sync(0xffffffffu, rs1, 1);
        rs1 += __shfl_xor_sync(0xffffffffu, rs1, 2);

        l0 = l0 * a0 + rs0;
        l1 = l1 * a1 + rs1;
        m0 = mn0; m1 = mn1;

#pragma unroll
        for (int nt = 0; nt < 8; nt++) {
            o[nt][0] *= a0; o[nt][1] *= a0;
            o[nt][2] *= a1; o[nt][3] *= a1;
        }

        __syncthreads();
#pragma unroll
        for (int nt = 0; nt < 8; nt++) {
            int col = nt * 8 + tig * 2;
            KPs[w * 16 + gid][col] = f2tf32(sc[nt][0]);
            KPs[w * 16 + gid][col + 1] = f2tf32(sc[nt][1]);
            KPs[w * 16 + gid + 8][col] = f2tf32(sc[nt][2]);
            KPs[w * 16 + gid + 8][col + 1] = f2tf32(sc[nt][3]);
        }
        __syncwarp();

#pragma unroll
        for (int kk = 0; kk < 8; kk++) {
            int k = kk * 8 + tig;
            uint32_t af[4];
            af[0] = KPs[w * 16 + gid][k];
            af[1] = KPs[w * 16 + gid + 8][k];
            af[2] = KPs[w * 16 + gid][k + 4];
            af[3] = KPs[w * 16 + gid + 8][k + 4];
#pragma unroll
            for (int nt = 0; nt < 8; nt++) {
                uint32_t bf[2];
                bf[0] = Vs[kk * 8 + tig][nt * 8 + gid];
                bf[1] = Vs[kk * 8 + tig + 4][nt * 8 + gid];
                mma_tf32(o[nt], af, bf);
            }
        }
    }

    float inv0 = 1.f / l0, inv1 = 1.f / l1;
    const size_t ob = ((size_t)b * SEQ + (size_t)qt * 64 + w * 16) * HEAD;
#pragma unroll
    for (int nt = 0; nt < 8; nt++) {
        int h = nt * 8 + tig * 2;
        *reinterpret_cast<float2*>(&out[ob + gid * HEAD + h]) =
            make_float2(o[nt][0] * inv0, o[nt][1] * inv0);
        *reinterpret_cast<float2*>(&out[ob + (gid + 8) * HEAD + h]) =
            make_float2(o[nt][2] * inv1, o[nt][3] * inv1);
    }
}

extern "C" void kernel_launch(void* const* d_in, const int* in_sizes, int n_in,
                              void* d_out, int out_size) {
    (void)in_sizes; (void)n_in; (void)out_size;
    const float* x = (const float*)d_in[0];
    const float* Wq = (const float*)d_in[1];
    const float* Wk = (const float*)d_in[2];
    const float* Wv = (const float*)d_in[3];
    float* out = (float*)d_out;

    cudaFuncSetAttribute(qkv_proj_kernel, cudaFuncAttributeMaxDynamicSharedMemorySize,
                         QKV_SMEM);

    wcvt_kernel<<<(192 * 512 + 255) / 256, 256>>>(Wq, Wk, Wv);
    qkv_proj_kernel<<<MROWS / 128, 512, QKV_SMEM>>>(x);
    attn_kernel<<<dim3(SEQ / 64, BATCH), 128>>>(out);
}

// round 9
// speedup vs baseline: 1.6870x; 1.6870x over previous
#include <cuda_runtime.h>
#include <cuda_fp16.h>
#include <cstdint>

#define BATCH 1024
#define SEQ   256
#define CDIM  512
#define HEAD  64
#define MROWS (BATCH * SEQ)
#define LOG2E 1.4426950408889634f

// Scratch (fp16): Q pre-scaled by 0.125*log2e; V stored transposed [b][h][t].
__device__ __half g_Q[(size_t)MROWS * HEAD];
__device__ __half g_K[(size_t)MROWS * HEAD];
__device__ __half g_Vt[(size_t)BATCH * HEAD * SEQ];
// Pre-transposed W as fp16: [N=192][K=512].
__device__ __half g_Wh[192 * 512];

// ---------------------------------------------------------------------------
// helpers (legacy pipe; MMA-instruction-rate-bound -> max K per instruction)
// ---------------------------------------------------------------------------
__device__ __forceinline__ void mma_f16(float d[4], const uint32_t a[4], const uint32_t b[2]) {
    asm volatile(
        "mma.sync.aligned.m16n8k16.row.col.f32.f16.f16.f32 "
        "{%0,%1,%2,%3}, {%4,%5,%6,%7}, {%8,%9}, {%0,%1,%2,%3};"
        : "+f"(d[0]), "+f"(d[1]), "+f"(d[2]), "+f"(d[3])
        : "r"(a[0]), "r"(a[1]), "r"(a[2]), "r"(a[3]), "r"(b[0]), "r"(b[1]));
}
__device__ __forceinline__ void ldsm_x4(uint32_t& r0, uint32_t& r1, uint32_t& r2,
                                        uint32_t& r3, uint32_t addr) {
    asm volatile("ldmatrix.sync.aligned.m8n8.x4.shared.b16 {%0,%1,%2,%3}, [%4];"
                 : "=r"(r0), "=r"(r1), "=r"(r2), "=r"(r3) : "r"(addr));
}
__device__ __forceinline__ uint32_t f2h2(float a, float b) {
    __half2 h = __floats2half2_rn(a, b);
    return *reinterpret_cast<uint32_t*>(&h);
}
__device__ __forceinline__ uint32_t smem_u32(const void* p) {
    uint32_t a;
    asm("{ .reg .u64 t; cvta.to.shared.u64 t, %1; cvt.u32.u64 %0, t; }" : "=r"(a) : "l"(p));
    return a;
}

// ---------------------------------------------------------------------------
// Prep: convert + transpose W into [192][512] fp16
// ---------------------------------------------------------------------------
__global__ void wcvt_kernel(const float* __restrict__ Wq, const float* __restrict__ Wk,
                            const float* __restrict__ Wv) {
    int i = blockIdx.x * 256 + threadIdx.x;
    if (i >= 192 * 512) return;
    int n = i >> 9, k = i & 511;
    const float* W = (n < 64) ? Wq : ((n < 128) ? Wk : Wv);
    g_Wh[i] = __float2half_rn(W[k * HEAD + (n & 63)]);
}

// ---------------------------------------------------------------------------
// Kernel 1: QKV projection, single-pass fp16 m16n8k16 (24 HMMA/warp/chunk).
// Block tile 128(M) x 192(N), BK=32, double-buffered. 512 threads:
// 16 warps = 4M x 4N, warp tile 32x48. ldmatrix.x4 everywhere.
// ---------------------------------------------------------------------------
#define A_OFF    0
#define B_OFF    10240
#define STAGE_B  25600
#define QKV_SMEM (2 * STAGE_B)   // 51200

__device__ __forceinline__ void qkv_ldg_a(const float* __restrict__ x, int row0,
                                          const int a_r[2], int a_q, int kc, float4 av[2]) {
#pragma unroll
    for (int i = 0; i < 2; i++)
        av[i] = *reinterpret_cast<const float4*>(
            &x[(size_t)(row0 + a_r[i]) * CDIM + kc + a_q * 4]);
}

__device__ __forceinline__ void qkv_cvt_a(char* stage, const int a_r[2], int a_q,
                                          const float4 av[2]) {
#pragma unroll
    for (int i = 0; i < 2; i++) {
        float4 v = av[i];
        *reinterpret_cast<uint2*>(stage + A_OFF + a_r[i] * 80 + a_q * 8) =
            make_uint2(f2h2(v.x, v.y), f2h2(v.z, v.w));
    }
}

__device__ __forceinline__ void qkv_cp_b(char* stage, int tid, int kc) {
    // B tile: 192 rows x 32 halfs (64B data in 80B stride) = 768 uint4.
#pragma unroll
    for (int s = 0; s < 2; s++) {
        int ui = s * 512 + tid;
        if (ui < 768) {
            int n = ui >> 2, ch = ui & 3;
            uint32_t dst;
            asm("{ .reg .u64 t; cvta.to.shared.u64 t, %1; cvt.u32.u64 %0, t; }"
                : "=r"(dst) : "l"(stage + B_OFF + n * 80 + ch * 16));
            asm volatile("cp.async.ca.shared.global [%0], [%1], 16;"
                         :: "r"(dst), "l"(g_Wh + n * 512 + kc + ch * 8));
        }
    }
}

__global__ void __launch_bounds__(512, 1)
qkv_proj_kernel(const float* __restrict__ x) {
    extern __shared__ char smem[];
    const uint32_t smem_b = smem_u32(smem);
    const int tid    = threadIdx.x;
    const int lane   = tid & 31;
    const int wid    = tid >> 5;
    const int warp_m = wid & 3;    // 0..3 -> M rows (x32)
    const int warp_n = wid >> 2;   // 0..3 -> N cols (x48)
    const int gid    = lane >> 2;
    const int tig    = lane & 3;
    const int row0   = blockIdx.x * 128;

    // ldmatrix lane-address bases (byte offsets within a stage)
    const uint32_t a_base =
        (uint32_t)((warp_m * 32 + (lane & 15)) * 80 + (lane >> 4) * 16);
    // B x4 = [nt_even k0-7, nt_even k8-15, nt_odd k0-7, nt_odd k8-15]
    const uint32_t b_base =
        (uint32_t)((warp_n * 48 + (lane & 7) + ((lane >> 4) & 1) * 8) * 80 +
                   ((lane >> 3) & 1) * 16);

    float acc[2][6][4];
#pragma unroll
    for (int mt = 0; mt < 2; mt++)
#pragma unroll
        for (int nt = 0; nt < 6; nt++)
#pragma unroll
            for (int i = 0; i < 4; i++) acc[mt][nt][i] = 0.f;

    float4 av[2];
    const int a_r[2] = {tid >> 3, (512 + tid) >> 3};
    const int a_q = tid & 7;

    // ---- prologue ----
    qkv_cp_b(smem, tid, 0);
    asm volatile("cp.async.commit_group;" ::: "memory");
    qkv_ldg_a(x, row0, a_r, a_q, 0, av);
    qkv_cvt_a(smem, a_r, a_q, av);

    for (int c = 0; c < 16; c++) {
        const int cur = (c & 1) * STAGE_B;
        asm volatile("cp.async.wait_group 0;" ::: "memory");
        __syncthreads();

        if (c + 1 < 16) {
            const int nxt = ((c + 1) & 1) * STAGE_B;
            const int kc = (c + 1) * 32;
            qkv_ldg_a(x, row0, a_r, a_q, kc, av);   // long-latency, used after MMAs
            qkv_cp_b(smem + nxt, tid, kc);
            asm volatile("cp.async.commit_group;" ::: "memory");
        }

        // ---- MMAs for chunk c: 10 LDSM.x4 + 24 HMMA per warp ----
        const uint32_t sstage = smem_b + cur;
#pragma unroll
        for (int kk = 0; kk < 2; kk++) {
            uint32_t ah[2][4];
            ldsm_x4(ah[0][0], ah[0][1], ah[0][2], ah[0][3],
                    sstage + A_OFF + a_base + kk * 32);
            ldsm_x4(ah[1][0], ah[1][1], ah[1][2], ah[1][3],
                    sstage + A_OFF + a_base + 1280 + kk * 32);
#pragma unroll
            for (int p = 0; p < 3; p++) {
                uint32_t bb[4];
                ldsm_x4(bb[0], bb[1], bb[2], bb[3],
                        sstage + B_OFF + b_base + p * 1280 + kk * 32);
                mma_f16(acc[0][2 * p],     ah[0], &bb[0]);
                mma_f16(acc[1][2 * p],     ah[1], &bb[0]);
                mma_f16(acc[0][2 * p + 1], ah[0], &bb[2]);
                mma_f16(acc[1][2 * p + 1], ah[1], &bb[2]);
            }
        }

        if (c + 1 < 16)
            qkv_cvt_a(smem + ((c + 1) & 1) * STAGE_B, a_r, a_q, av);
    }

    // ---- writeback fp16: Q pre-scaled by 0.125*log2e; V transposed ----
    const float qs = 0.125f * LOG2E;
#pragma unroll
    for (int mt = 0; mt < 2; mt++) {
        int r = row0 + warp_m * 32 + mt * 16 + gid;
#pragma unroll
        for (int nt = 0; nt < 6; nt++) {
            int n = warp_n * 48 + nt * 8 + tig * 2;
            if (n < 128) {
                __half* dst = (n < 64) ? g_Q : g_K;
                float s = (n < 64) ? qs : 1.0f;
                int h = n & 63;
                *reinterpret_cast<uint32_t*>(&dst[(size_t)r * HEAD + h]) =
                    f2h2(acc[mt][nt][0] * s, acc[mt][nt][1] * s);
                *reinterpret_cast<uint32_t*>(&dst[(size_t)(r + 8) * HEAD + h]) =
                    f2h2(acc[mt][nt][2] * s, acc[mt][nt][3] * s);
            } else {
                int h = n - 128;
                int b0 = r >> 8, t0 = r & 255;
                int b1 = (r + 8) >> 8, t1 = (r + 8) & 255;
                g_Vt[((size_t)b0 * HEAD + h)     * SEQ + t0] = __float2half_rn(acc[mt][nt][0]);
                g_Vt[((size_t)b0 * HEAD + h + 1) * SEQ + t0] = __float2half_rn(acc[mt][nt][1]);
                g_Vt[((size_t)b1 * HEAD + h)     * SEQ + t1] = __float2half_rn(acc[mt][nt][2]);
                g_Vt[((size_t)b1 * HEAD + h + 1) * SEQ + t1] = __float2half_rn(acc[mt][nt][3]);
            }
        }
    }
}

// ---------------------------------------------------------------------------
// Kernel 2: causal flash attention, fp16 m16n8k16 (32+32 HMMA/warp/j-tile).
// Scores in log2 domain (Q pre-scaled); softmax via exp2f. fp32 accum/softmax.
// ---------------------------------------------------------------------------
__global__ void __launch_bounds__(128, 4)
attn_kernel(float* __restrict__ out) {
    __shared__ uint32_t KPs[64][36];  // K tile (keys x h-pairs), reused as P
    __shared__ uint32_t Vs[64][36];   // V^T tile (h x key-pairs)

    const int b = blockIdx.y;
    const int qt = (gridDim.x - 1) - blockIdx.x;  // heavy tiles first
    const int tid = threadIdx.x;
    const int lane = tid & 31;
    const int w = tid >> 5;
    const int gid = lane >> 2;
    const int tig = lane & 3;

    // Q fragments: 4 k16-steps x 4 regs (half2)
    uint32_t qf[4][4];
    {
        const size_t qbase = ((size_t)b * SEQ + (size_t)qt * 64 + w * 16) * HEAD;
#pragma unroll
        for (int kk = 0; kk < 4; kk++) {
            int h = kk * 16 + tig * 2;
            qf[kk][0] = *reinterpret_cast<const uint32_t*>(&g_Q[qbase + gid * HEAD + h]);
            qf[kk][1] = *reinterpret_cast<const uint32_t*>(&g_Q[qbase + (gid + 8) * HEAD + h]);
            qf[kk][2] = *reinterpret_cast<const uint32_t*>(&g_Q[qbase + gid * HEAD + h + 8]);
            qf[kk][3] = *reinterpret_cast<const uint32_t*>(&g_Q[qbase + (gid + 8) * HEAD + h + 8]);
        }
    }

    float m0 = -1e30f, m1 = -1e30f, l0 = 0.f, l1 = 0.f;
    float o[8][4];
#pragma unroll
    for (int nt = 0; nt < 8; nt++)
#pragma unroll
        for (int i = 0; i < 4; i++) o[nt][i] = 0.f;

    for (int j = 0; j <= qt; j++) {
        __syncthreads();  // prev iteration's P/V reads done before overwrite
        // K tile: [key][h] halfs; V^T tile: [h][key] halfs
#pragma unroll
        for (int s = 0; s < 4; s++) {
            int idx4 = s * 128 + tid;
            int r8 = idx4 >> 3, q8 = idx4 & 7;
            *reinterpret_cast<uint4*>(&KPs[r8][q8 * 4]) =
                *reinterpret_cast<const uint4*>(
                    &g_K[((size_t)b * SEQ + j * 64 + r8) * HEAD + q8 * 8]);
            *reinterpret_cast<uint4*>(&Vs[r8][q8 * 4]) =
                *reinterpret_cast<const uint4*>(
                    &g_Vt[((size_t)b * HEAD + r8) * SEQ + j * 64 + q8 * 8]);
        }
        __syncthreads();

        // ---- S = Q @ K^T : 16x64 per warp (32 HMMA) ----
        float sc[8][4];
#pragma unroll
        for (int nt = 0; nt < 8; nt++)
#pragma unroll
            for (int i = 0; i < 4; i++) sc[nt][i] = 0.f;

#pragma unroll
        for (int kk = 0; kk < 4; kk++) {
#pragma unroll
            for (int nt = 0; nt < 8; nt++) {
                uint32_t bf[2];
                bf[0] = KPs[nt * 8 + gid][kk * 8 + tig];
                bf[1] = KPs[nt * 8 + gid][kk * 8 + tig + 4];
                mma_f16(sc[nt], qf[kk], bf);
            }
        }

        if (j == qt) {
            int q0 = w * 16 + gid, q1 = q0 + 8;
#pragma unroll
            for (int nt = 0; nt < 8; nt++) {
                int kc = nt * 8 + tig * 2;
                if (kc > q0) sc[nt][0] = -1e30f;
                if (kc + 1 > q0) sc[nt][1] = -1e30f;
                if (kc > q1) sc[nt][2] = -1e30f;
                if (kc + 1 > q1) sc[nt][3] = -1e30f;
            }
        }

        float rm0 = -1e30f, rm1 = -1e30f;
#pragma unroll
        for (int nt = 0; nt < 8; nt++) {
            rm0 = fmaxf(rm0, fmaxf(sc[nt][0], sc[nt][1]));
            rm1 = fmaxf(rm1, fmaxf(sc[nt][2], sc[nt][3]));
        }
        rm0 = fmaxf(rm0, __shfl_xor_sync(0xffffffffu, rm0, 1));
        rm0 = fmaxf(rm0, __shfl_xor_sync(0xffffffffu, rm0, 2));
        rm1 = fmaxf(rm1, __shfl_xor_sync(0xffffffffu, rm1, 1));
        rm1 = fmaxf(rm1, __shfl_xor_sync(0xffffffffu, rm1, 2));

        float mn0 = fmaxf(m0, rm0), mn1 = fmaxf(m1, rm1);
        float a0 = exp2f(m0 - mn0), a1 = exp2f(m1 - mn1);

        float rs0 = 0.f, rs1 = 0.f;
#pragma unroll
        for (int nt = 0; nt < 8; nt++) {
            sc[nt][0] = exp2f(sc[nt][0] - mn0);
            sc[nt][1] = exp2f(sc[nt][1] - mn0);
            sc[nt][2] = exp2f(sc[nt][2] - mn1);
            sc[nt][3] = exp2f(sc[nt][3] - mn1);
            rs0 += sc[nt][0] + sc[nt][1];
            rs1 += sc[nt][2] + sc[nt][3];
        }
        rs0 += __shfl_xor_sync(0xffffffffu, rs0, 1);
        rs0 += __shfl_xor_sync(0xffffffffu, rs0, 2);
        rs1 += __shfl_xor_sync(0xffffffffu, rs1, 1);
        rs1 += __shfl_xor_sync(0xffffffffu, rs1, 2);

        l0 = l0 * a0 + rs0;
        l1 = l1 * a1 + rs1;
        m0 = mn0; m1 = mn1;

#pragma unroll
        for (int nt = 0; nt < 8; nt++) {
            o[nt][0] *= a0; o[nt][1] *= a0;
            o[nt][2] *= a1; o[nt][3] *= a1;
        }

        __syncthreads();  // all warps done reading K tile before P overwrites
#pragma unroll
        for (int nt = 0; nt < 8; nt++) {
            KPs[w * 16 + gid][nt * 4 + tig]     = f2h2(sc[nt][0], sc[nt][1]);
            KPs[w * 16 + gid + 8][nt * 4 + tig] = f2h2(sc[nt][2], sc[nt][3]);
        }
        __syncwarp();  // P rows are warp-private

        // ---- O += P @ V : 32 HMMA ----
#pragma unroll
        for (int kk = 0; kk < 4; kk++) {
            uint32_t af[4];
            af[0] = KPs[w * 16 + gid][kk * 8 + tig];
            af[1] = KPs[w * 16 + gid + 8][kk * 8 + tig];
            af[2] = KPs[w * 16 + gid][kk * 8 + tig + 4];
            af[3] = KPs[w * 16 + gid + 8][kk * 8 + tig + 4];
#pragma unroll
            for (int nt = 0; nt < 8; nt++) {
                uint32_t bf[2];
                bf[0] = Vs[nt * 8 + gid][kk * 8 + tig];
                bf[1] = Vs[nt * 8 + gid][kk * 8 + tig + 4];
                mma_f16(o[nt], af, bf);
            }
        }
    }

    // ---- normalize and write out (fp32) ----
    float inv0 = 1.f / l0, inv1 = 1.f / l1;
    const size_t ob = ((size_t)b * SEQ + (size_t)qt * 64 + w * 16) * HEAD;
#pragma unroll
    for (int nt = 0; nt < 8; nt++) {
        int h = nt * 8 + tig * 2;
        *reinterpret_cast<float2*>(&out[ob + gid * HEAD + h]) =
            make_float2(o[nt][0] * inv0, o[nt][1] * inv0);
        *reinterpret_cast<float2*>(&out[ob + (gid + 8) * HEAD + h]) =
            make_float2(o[nt][2] * inv1, o[nt][3] * inv1);
    }
}

extern "C" void kernel_launch(void* const* d_in, const int* in_sizes, int n_in,
                              void* d_out, int out_size) {
    (void)in_sizes; (void)n_in; (void)out_size;
    const float* x = (const float*)d_in[0];
    const float* Wq = (const float*)d_in[1];
    const float* Wk = (const float*)d_in[2];
    const float* Wv = (const float*)d_in[3];
    float* out = (float*)d_out;

    cudaFuncSetAttribute(qkv_proj_kernel, cudaFuncAttributeMaxDynamicSharedMemorySize,
                         QKV_SMEM);

    wcvt_kernel<<<(192 * 512 + 255) / 256, 256>>>(Wq, Wk, Wv);
    qkv_proj_kernel<<<MROWS / 128, 512, QKV_SMEM>>>(x);
    attn_kernel<<<dim3(SEQ / 64, BATCH), 128>>>(out);
}

// round 10
// speedup vs baseline: 1.6996x; 1.0075x over previous
#include <cuda_runtime.h>
#include <cuda_fp16.h>
#include <cstdint>

#define BATCH 1024
#define SEQ   256
#define CDIM  512
#define HEAD  64
#define MROWS (BATCH * SEQ)
#define LOG2E 1.4426950408889634f

// Scratch (fp16): Q pre-scaled by 0.125*log2e; V stored transposed [b][h][t].
__device__ __half g_Q[(size_t)MROWS * HEAD];
__device__ __half g_K[(size_t)MROWS * HEAD];
__device__ __half g_Vt[(size_t)BATCH * HEAD * SEQ];
// Pre-transposed W as fp16: [N=192][K=512].
__device__ __half g_Wh[192 * 512];

// ---------------------------------------------------------------------------
// helpers (legacy pipe; MMA-instruction-rate-bound -> max K per instruction)
// ---------------------------------------------------------------------------
__device__ __forceinline__ void mma_f16(float d[4], const uint32_t a[4], const uint32_t b[2]) {
    asm volatile(
        "mma.sync.aligned.m16n8k16.row.col.f32.f16.f16.f32 "
        "{%0,%1,%2,%3}, {%4,%5,%6,%7}, {%8,%9}, {%0,%1,%2,%3};"
        : "+f"(d[0]), "+f"(d[1]), "+f"(d[2]), "+f"(d[3])
        : "r"(a[0]), "r"(a[1]), "r"(a[2]), "r"(a[3]), "r"(b[0]), "r"(b[1]));
}
__device__ __forceinline__ void ldsm_x4(uint32_t& r0, uint32_t& r1, uint32_t& r2,
                                        uint32_t& r3, uint32_t addr) {
    asm volatile("ldmatrix.sync.aligned.m8n8.x4.shared.b16 {%0,%1,%2,%3}, [%4];"
                 : "=r"(r0), "=r"(r1), "=r"(r2), "=r"(r3) : "r"(addr));
}
__device__ __forceinline__ uint32_t f2h2(float a, float b) {
    __half2 h = __floats2half2_rn(a, b);
    return *reinterpret_cast<uint32_t*>(&h);
}
__device__ __forceinline__ uint32_t smem_u32(const void* p) {
    uint32_t a;
    asm("{ .reg .u64 t; cvta.to.shared.u64 t, %1; cvt.u32.u64 %0, t; }" : "=r"(a) : "l"(p));
    return a;
}

// ---------------------------------------------------------------------------
// Prep: convert + transpose W into [192][512] fp16
// ---------------------------------------------------------------------------
__global__ void wcvt_kernel(const float* __restrict__ Wq, const float* __restrict__ Wk,
                            const float* __restrict__ Wv) {
    int i = blockIdx.x * 256 + threadIdx.x;
    if (i >= 192 * 512) return;
    int n = i >> 9, k = i & 511;
    const float* W = (n < 64) ? Wq : ((n < 128) ? Wk : Wv);
    g_Wh[i] = __float2half_rn(W[k * HEAD + (n & 63)]);
}

// ---------------------------------------------------------------------------
// Kernel 1: QKV projection, single-pass fp16 m16n8k16 (unchanged from R9:
// ~90% of the measured HMMA instruction-rate ceiling).
// ---------------------------------------------------------------------------
#define A_OFF    0
#define B_OFF    10240
#define STAGE_B  25600
#define QKV_SMEM (2 * STAGE_B)   // 51200

__device__ __forceinline__ void qkv_ldg_a(const float* __restrict__ x, int row0,
                                          const int a_r[2], int a_q, int kc, float4 av[2]) {
#pragma unroll
    for (int i = 0; i < 2; i++)
        av[i] = *reinterpret_cast<const float4*>(
            &x[(size_t)(row0 + a_r[i]) * CDIM + kc + a_q * 4]);
}

__device__ __forceinline__ void qkv_cvt_a(char* stage, const int a_r[2], int a_q,
                                          const float4 av[2]) {
#pragma unroll
    for (int i = 0; i < 2; i++) {
        float4 v = av[i];
        *reinterpret_cast<uint2*>(stage + A_OFF + a_r[i] * 80 + a_q * 8) =
            make_uint2(f2h2(v.x, v.y), f2h2(v.z, v.w));
    }
}

__device__ __forceinline__ void qkv_cp_b(char* stage, int tid, int kc) {
#pragma unroll
    for (int s = 0; s < 2; s++) {
        int ui = s * 512 + tid;
        if (ui < 768) {
            int n = ui >> 2, ch = ui & 3;
            uint32_t dst;
            asm("{ .reg .u64 t; cvta.to.shared.u64 t, %1; cvt.u32.u64 %0, t; }"
                : "=r"(dst) : "l"(stage + B_OFF + n * 80 + ch * 16));
            asm volatile("cp.async.ca.shared.global [%0], [%1], 16;"
                         :: "r"(dst), "l"(g_Wh + n * 512 + kc + ch * 8));
        }
    }
}

__global__ void __launch_bounds__(512, 1)
qkv_proj_kernel(const float* __restrict__ x) {
    extern __shared__ char smem[];
    const uint32_t smem_b = smem_u32(smem);
    const int tid    = threadIdx.x;
    const int lane   = tid & 31;
    const int wid    = tid >> 5;
    const int warp_m = wid & 3;
    const int warp_n = wid >> 2;
    const int gid    = lane >> 2;
    const int tig    = lane & 3;
    const int row0   = blockIdx.x * 128;

    const uint32_t a_base =
        (uint32_t)((warp_m * 32 + (lane & 15)) * 80 + (lane >> 4) * 16);
    const uint32_t b_base =
        (uint32_t)((warp_n * 48 + (lane & 7) + ((lane >> 4) & 1) * 8) * 80 +
                   ((lane >> 3) & 1) * 16);

    float acc[2][6][4];
#pragma unroll
    for (int mt = 0; mt < 2; mt++)
#pragma unroll
        for (int nt = 0; nt < 6; nt++)
#pragma unroll
            for (int i = 0; i < 4; i++) acc[mt][nt][i] = 0.f;

    float4 av[2];
    const int a_r[2] = {tid >> 3, (512 + tid) >> 3};
    const int a_q = tid & 7;

    qkv_cp_b(smem, tid, 0);
    asm volatile("cp.async.commit_group;" ::: "memory");
    qkv_ldg_a(x, row0, a_r, a_q, 0, av);
    qkv_cvt_a(smem, a_r, a_q, av);

    for (int c = 0; c < 16; c++) {
        const int cur = (c & 1) * STAGE_B;
        asm volatile("cp.async.wait_group 0;" ::: "memory");
        __syncthreads();

        if (c + 1 < 16) {
            const int nxt = ((c + 1) & 1) * STAGE_B;
            const int kc = (c + 1) * 32;
            qkv_ldg_a(x, row0, a_r, a_q, kc, av);
            qkv_cp_b(smem + nxt, tid, kc);
            asm volatile("cp.async.commit_group;" ::: "memory");
        }

        const uint32_t sstage = smem_b + cur;
#pragma unroll
        for (int kk = 0; kk < 2; kk++) {
            uint32_t ah[2][4];
            ldsm_x4(ah[0][0], ah[0][1], ah[0][2], ah[0][3],
                    sstage + A_OFF + a_base + kk * 32);
            ldsm_x4(ah[1][0], ah[1][1], ah[1][2], ah[1][3],
                    sstage + A_OFF + a_base + 1280 + kk * 32);
#pragma unroll
            for (int p = 0; p < 3; p++) {
                uint32_t bb[4];
                ldsm_x4(bb[0], bb[1], bb[2], bb[3],
                        sstage + B_OFF + b_base + p * 1280 + kk * 32);
                mma_f16(acc[0][2 * p],     ah[0], &bb[0]);
                mma_f16(acc[1][2 * p],     ah[1], &bb[0]);
                mma_f16(acc[0][2 * p + 1], ah[0], &bb[2]);
                mma_f16(acc[1][2 * p + 1], ah[1], &bb[2]);
            }
        }

        if (c + 1 < 16)
            qkv_cvt_a(smem + ((c + 1) & 1) * STAGE_B, a_r, a_q, av);
    }

    const float qs = 0.125f * LOG2E;
#pragma unroll
    for (int mt = 0; mt < 2; mt++) {
        int r = row0 + warp_m * 32 + mt * 16 + gid;
#pragma unroll
        for (int nt = 0; nt < 6; nt++) {
            int n = warp_n * 48 + nt * 8 + tig * 2;
            if (n < 128) {
                __half* dst = (n < 64) ? g_Q : g_K;
                float s = (n < 64) ? qs : 1.0f;
                int h = n & 63;
                *reinterpret_cast<uint32_t*>(&dst[(size_t)r * HEAD + h]) =
                    f2h2(acc[mt][nt][0] * s, acc[mt][nt][1] * s);
                *reinterpret_cast<uint32_t*>(&dst[(size_t)(r + 8) * HEAD + h]) =
                    f2h2(acc[mt][nt][2] * s, acc[mt][nt][3] * s);
            } else {
                int h = n - 128;
                int b0 = r >> 8, t0 = r & 255;
                int b1 = (r + 8) >> 8, t1 = (r + 8) & 255;
                g_Vt[((size_t)b0 * HEAD + h)     * SEQ + t0] = __float2half_rn(acc[mt][nt][0]);
                g_Vt[((size_t)b0 * HEAD + h + 1) * SEQ + t0] = __float2half_rn(acc[mt][nt][1]);
                g_Vt[((size_t)b1 * HEAD + h)     * SEQ + t1] = __float2half_rn(acc[mt][nt][2]);
                g_Vt[((size_t)b1 * HEAD + h + 1) * SEQ + t1] = __float2half_rn(acc[mt][nt][3]);
            }
        }
    }
}

// ---------------------------------------------------------------------------
// Kernel 2: causal flash attention, fp16 m16n8k16.
// 128 q-rows per block (8 warps); per-warp causal skip; P kept in registers
// (S-output layout == PV A-layout after fp16 pairwise pack). One K/V tile
// buffer; 2 syncthreads per j-tile; j-iterations per batch: 6 (was 10).
// ---------------------------------------------------------------------------
__global__ void __launch_bounds__(256, 2)
attn_kernel(float* __restrict__ out) {
    __shared__ uint32_t Ks[64][36];  // K tile: [key][h-pair]
    __shared__ uint32_t Vs[64][36];  // V^T tile: [h][key-pair]

    const int b = blockIdx.y;
    const int qt2 = 1 - blockIdx.x;      // heavy half (4 j-tiles) first
    const int tid = threadIdx.x;
    const int lane = tid & 31;
    const int w = tid >> 5;              // warp 0..7 -> q rows qt2*128 + w*16
    const int gid = lane >> 2;
    const int tig = lane & 3;
    const int jmax_w = 2 * qt2 + (w >> 2);   // last j-tile this warp sees
    const int jend = 2 * qt2 + 1;            // block's last j-tile

    // Q fragments: 4 k16-steps x 4 regs (half2); Q pre-scaled by 0.125*log2e
    uint32_t qf[4][4];
    {
        const size_t qbase = ((size_t)b * SEQ + (size_t)qt2 * 128 + w * 16) * HEAD;
#pragma unroll
        for (int kk = 0; kk < 4; kk++) {
            int h = kk * 16 + tig * 2;
            qf[kk][0] = *reinterpret_cast<const uint32_t*>(&g_Q[qbase + gid * HEAD + h]);
            qf[kk][1] = *reinterpret_cast<const uint32_t*>(&g_Q[qbase + (gid + 8) * HEAD + h]);
            qf[kk][2] = *reinterpret_cast<const uint32_t*>(&g_Q[qbase + gid * HEAD + h + 8]);
            qf[kk][3] = *reinterpret_cast<const uint32_t*>(&g_Q[qbase + (gid + 8) * HEAD + h + 8]);
        }
    }

    float m0 = -1e30f, m1 = -1e30f, l0 = 0.f, l1 = 0.f;
    float o[8][4];
#pragma unroll
    for (int nt = 0; nt < 8; nt++)
#pragma unroll
        for (int i = 0; i < 4; i++) o[nt][i] = 0.f;

    for (int j = 0; j <= jend; j++) {
        __syncthreads();  // all warps done with previous tile before overwrite
        // K tile [key][h], V^T tile [h][key]: 512+512 uint4, 256 threads x 2+2
#pragma unroll
        for (int s = 0; s < 2; s++) {
            int idx4 = s * 256 + tid;
            int r8 = idx4 >> 3, q8 = idx4 & 7;
            *reinterpret_cast<uint4*>(&Ks[r8][q8 * 4]) =
                *reinterpret_cast<const uint4*>(
                    &g_K[((size_t)b * SEQ + j * 64 + r8) * HEAD + q8 * 8]);
            *reinterpret_cast<uint4*>(&Vs[r8][q8 * 4]) =
                *reinterpret_cast<const uint4*>(
                    &g_Vt[((size_t)b * HEAD + r8) * SEQ + j * 64 + q8 * 8]);
        }
        __syncthreads();

        if (j > jmax_w) continue;   // causally empty for this warp

        // ---- S = Q @ K^T : 16x64 (32 HMMA) ----
        float sc[8][4];
#pragma unroll
        for (int nt = 0; nt < 8; nt++)
#pragma unroll
            for (int i = 0; i < 4; i++) sc[nt][i] = 0.f;

#pragma unroll
        for (int kk = 0; kk < 4; kk++) {
#pragma unroll
            for (int nt = 0; nt < 8; nt++) {
                uint32_t bf[2];
                bf[0] = Ks[nt * 8 + gid][kk * 8 + tig];
                bf[1] = Ks[nt * 8 + gid][kk * 8 + tig + 4];
                mma_f16(sc[nt], qf[kk], bf);
            }
        }

        // ---- causal mask on this warp's diagonal tile ----
        if (j == jmax_w) {
            int q0 = (w & 3) * 16 + gid, q1 = q0 + 8;  // row within the 64-row subtile
#pragma unroll
            for (int nt = 0; nt < 8; nt++) {
                int kc = nt * 8 + tig * 2;
                if (kc > q0) sc[nt][0] = -1e30f;
                if (kc + 1 > q0) sc[nt][1] = -1e30f;
                if (kc > q1) sc[nt][2] = -1e30f;
                if (kc + 1 > q1) sc[nt][3] = -1e30f;
            }
        }

        // ---- online softmax (log2 domain; fp32) ----
        float rm0 = -1e30f, rm1 = -1e30f;
#pragma unroll
        for (int nt = 0; nt < 8; nt++) {
            rm0 = fmaxf(rm0, fmaxf(sc[nt][0], sc[nt][1]));
            rm1 = fmaxf(rm1, fmaxf(sc[nt][2], sc[nt][3]));
        }
        rm0 = fmaxf(rm0, __shfl_xor_sync(0xffffffffu, rm0, 1));
        rm0 = fmaxf(rm0, __shfl_xor_sync(0xffffffffu, rm0, 2));
        rm1 = fmaxf(rm1, __shfl_xor_sync(0xffffffffu, rm1, 1));
        rm1 = fmaxf(rm1, __shfl_xor_sync(0xffffffffu, rm1, 2));

        float mn0 = fmaxf(m0, rm0), mn1 = fmaxf(m1, rm1);
        float a0 = exp2f(m0 - mn0), a1 = exp2f(m1 - mn1);

        float rs0 = 0.f, rs1 = 0.f;
#pragma unroll
        for (int nt = 0; nt < 8; nt++) {
            sc[nt][0] = exp2f(sc[nt][0] - mn0);
            sc[nt][1] = exp2f(sc[nt][1] - mn0);
            sc[nt][2] = exp2f(sc[nt][2] - mn1);
            sc[nt][3] = exp2f(sc[nt][3] - mn1);
            rs0 += sc[nt][0] + sc[nt][1];
            rs1 += sc[nt][2] + sc[nt][3];
        }
        rs0 += __shfl_xor_sync(0xffffffffu, rs0, 1);
        rs0 += __shfl_xor_sync(0xffffffffu, rs0, 2);
        rs1 += __shfl_xor_sync(0xffffffffu, rs1, 1);
        rs1 += __shfl_xor_sync(0xffffffffu, rs1, 2);

        l0 = l0 * a0 + rs0;
        l1 = l1 * a1 + rs1;
        m0 = mn0; m1 = mn1;

#pragma unroll
        for (int nt = 0; nt < 8; nt++) {
            o[nt][0] *= a0; o[nt][1] *= a0;
            o[nt][2] *= a1; o[nt][3] *= a1;
        }

        // ---- O += P @ V : P stays in registers (C-layout == A-layout) ----
#pragma unroll
        for (int kk = 0; kk < 4; kk++) {
            uint32_t af[4];
            af[0] = f2h2(sc[2 * kk][0],     sc[2 * kk][1]);
            af[1] = f2h2(sc[2 * kk][2],     sc[2 * kk][3]);
            af[2] = f2h2(sc[2 * kk + 1][0], sc[2 * kk + 1][1]);
            af[3] = f2h2(sc[2 * kk + 1][2], sc[2 * kk + 1][3]);
#pragma unroll
            for (int nt = 0; nt < 8; nt++) {
                uint32_t bf[2];
                bf[0] = Vs[nt * 8 + gid][kk * 8 + tig];
                bf[1] = Vs[nt * 8 + gid][kk * 8 + tig + 4];
                mma_f16(o[nt], af, bf);
            }
        }
    }

    // ---- normalize and write out (fp32) ----
    float inv0 = 1.f / l0, inv1 = 1.f / l1;
    const size_t ob = ((size_t)b * SEQ + (size_t)qt2 * 128 + w * 16) * HEAD;
#pragma unroll
    for (int nt = 0; nt < 8; nt++) {
        int h = nt * 8 + tig * 2;
        *reinterpret_cast<float2*>(&out[ob + gid * HEAD + h]) =
            make_float2(o[nt][0] * inv0, o[nt][1] * inv0);
        *reinterpret_cast<float2*>(&out[ob + (gid + 8) * HEAD + h]) =
            make_float2(o[nt][2] * inv1, o[nt][3] * inv1);
    }
}

extern "C" void kernel_launch(void* const* d_in, const int* in_sizes, int n_in,
                              void* d_out, int out_size) {
    (void)in_sizes; (void)n_in; (void)out_size;
    const float* x = (const float*)d_in[0];
    const float* Wq = (const float*)d_in[1];
    const float* Wk = (const float*)d_in[2];
    const float* Wv = (const float*)d_in[3];
    float* out = (float*)d_out;

    cudaFuncSetAttribute(qkv_proj_kernel, cudaFuncAttributeMaxDynamicSharedMemorySize,
                         QKV_SMEM);

    wcvt_kernel<<<(192 * 512 + 255) / 256, 256>>>(Wq, Wk, Wv);
    qkv_proj_kernel<<<MROWS / 128, 512, QKV_SMEM>>>(x);
    attn_kernel<<<dim3(2, BATCH), 256>>>(out);
}

// round 11
// speedup vs baseline: 1.7070x; 1.0044x over previous
#include <cuda_runtime.h>
#include <cuda_fp16.h>
#include <cstdint>

#define BATCH 1024
#define SEQ   256
#define CDIM  512
#define HEAD  64
#define MROWS (BATCH * SEQ)
#define LOG2E 1.4426950408889634f

// Scratch (fp16): Q pre-scaled by 0.125*log2e; V stored transposed [b][h][t].
__device__ __half g_Q[(size_t)MROWS * HEAD];
__device__ __half g_K[(size_t)MROWS * HEAD];
__device__ __half g_Vt[(size_t)BATCH * HEAD * SEQ];
// Pre-transposed W as fp16: [N=192][K=512].
__device__ __half g_Wh[192 * 512];

// ---------------------------------------------------------------------------
// helpers (legacy pipe; MMA-instruction-rate-bound -> max K per instruction)
// ---------------------------------------------------------------------------
__device__ __forceinline__ void mma_f16(float d[4], const uint32_t a[4], const uint32_t b[2]) {
    asm volatile(
        "mma.sync.aligned.m16n8k16.row.col.f32.f16.f16.f32 "
        "{%0,%1,%2,%3}, {%4,%5,%6,%7}, {%8,%9}, {%0,%1,%2,%3};"
        : "+f"(d[0]), "+f"(d[1]), "+f"(d[2]), "+f"(d[3])
        : "r"(a[0]), "r"(a[1]), "r"(a[2]), "r"(a[3]), "r"(b[0]), "r"(b[1]));
}
__device__ __forceinline__ void ldsm_x4(uint32_t& r0, uint32_t& r1, uint32_t& r2,
                                        uint32_t& r3, uint32_t addr) {
    asm volatile("ldmatrix.sync.aligned.m8n8.x4.shared.b16 {%0,%1,%2,%3}, [%4];"
                 : "=r"(r0), "=r"(r1), "=r"(r2), "=r"(r3) : "r"(addr));
}
__device__ __forceinline__ uint32_t f2h2(float a, float b) {
    __half2 h = __floats2half2_rn(a, b);
    return *reinterpret_cast<uint32_t*>(&h);
}
__device__ __forceinline__ float ex2(float x) {
    float r;
    asm("ex2.approx.f32 %0, %1;" : "=f"(r) : "f"(x));
    return r;
}
__device__ __forceinline__ uint32_t smem_u32(const void* p) {
    uint32_t a;
    asm("{ .reg .u64 t; cvta.to.shared.u64 t, %1; cvt.u32.u64 %0, t; }" : "=r"(a) : "l"(p));
    return a;
}
__device__ __forceinline__ void cp16(uint32_t dst, const void* src) {
    asm volatile("cp.async.cg.shared.global [%0], [%1], 16;" :: "r"(dst), "l"(src));
}

// ---------------------------------------------------------------------------
// Prep: convert + transpose W into [192][512] fp16
// ---------------------------------------------------------------------------
__global__ void wcvt_kernel(const float* __restrict__ Wq, const float* __restrict__ Wk,
                            const float* __restrict__ Wv) {
    int i = blockIdx.x * 256 + threadIdx.x;
    if (i >= 192 * 512) return;
    int n = i >> 9, k = i & 511;
    const float* W = (n < 64) ? Wq : ((n < 128) ? Wk : Wv);
    g_Wh[i] = __float2half_rn(W[k * HEAD + (n & 63)]);
}

// ---------------------------------------------------------------------------
// Kernel 1: QKV projection, single-pass fp16 m16n8k16 (unchanged from R9/R10:
// ~90% of the measured HMMA instruction-rate ceiling).
// ---------------------------------------------------------------------------
#define A_OFF    0
#define B_OFF    10240
#define STAGE_B  25600
#define QKV_SMEM (2 * STAGE_B)   // 51200

__device__ __forceinline__ void qkv_ldg_a(const float* __restrict__ x, int row0,
                                          const int a_r[2], int a_q, int kc, float4 av[2]) {
#pragma unroll
    for (int i = 0; i < 2; i++)
        av[i] = *reinterpret_cast<const float4*>(
            &x[(size_t)(row0 + a_r[i]) * CDIM + kc + a_q * 4]);
}

__device__ __forceinline__ void qkv_cvt_a(char* stage, const int a_r[2], int a_q,
                                          const float4 av[2]) {
#pragma unroll
    for (int i = 0; i < 2; i++) {
        float4 v = av[i];
        *reinterpret_cast<uint2*>(stage + A_OFF + a_r[i] * 80 + a_q * 8) =
            make_uint2(f2h2(v.x, v.y), f2h2(v.z, v.w));
    }
}

__device__ __forceinline__ void qkv_cp_b(char* stage, int tid, int kc) {
#pragma unroll
    for (int s = 0; s < 2; s++) {
        int ui = s * 512 + tid;
        if (ui < 768) {
            int n = ui >> 2, ch = ui & 3;
            uint32_t dst;
            asm("{ .reg .u64 t; cvta.to.shared.u64 t, %1; cvt.u32.u64 %0, t; }"
                : "=r"(dst) : "l"(stage + B_OFF + n * 80 + ch * 16));
            asm volatile("cp.async.ca.shared.global [%0], [%1], 16;"
                         :: "r"(dst), "l"(g_Wh + n * 512 + kc + ch * 8));
        }
    }
}

__global__ void __launch_bounds__(512, 1)
qkv_proj_kernel(const float* __restrict__ x) {
    extern __shared__ char smem[];
    const uint32_t smem_b = smem_u32(smem);
    const int tid    = threadIdx.x;
    const int lane   = tid & 31;
    const int wid    = tid >> 5;
    const int warp_m = wid & 3;
    const int warp_n = wid >> 2;
    const int gid    = lane >> 2;
    const int tig    = lane & 3;
    const int row0   = blockIdx.x * 128;

    const uint32_t a_base =
        (uint32_t)((warp_m * 32 + (lane & 15)) * 80 + (lane >> 4) * 16);
    const uint32_t b_base =
        (uint32_t)((warp_n * 48 + (lane & 7) + ((lane >> 4) & 1) * 8) * 80 +
                   ((lane >> 3) & 1) * 16);

    float acc[2][6][4];
#pragma unroll
    for (int mt = 0; mt < 2; mt++)
#pragma unroll
        for (int nt = 0; nt < 6; nt++)
#pragma unroll
            for (int i = 0; i < 4; i++) acc[mt][nt][i] = 0.f;

    float4 av[2];
    const int a_r[2] = {tid >> 3, (512 + tid) >> 3};
    const int a_q = tid & 7;

    qkv_cp_b(smem, tid, 0);
    asm volatile("cp.async.commit_group;" ::: "memory");
    qkv_ldg_a(x, row0, a_r, a_q, 0, av);
    qkv_cvt_a(smem, a_r, a_q, av);

    for (int c = 0; c < 16; c++) {
        const int cur = (c & 1) * STAGE_B;
        asm volatile("cp.async.wait_group 0;" ::: "memory");
        __syncthreads();

        if (c + 1 < 16) {
            const int nxt = ((c + 1) & 1) * STAGE_B;
            const int kc = (c + 1) * 32;
            qkv_ldg_a(x, row0, a_r, a_q, kc, av);
            qkv_cp_b(smem + nxt, tid, kc);
            asm volatile("cp.async.commit_group;" ::: "memory");
        }

        const uint32_t sstage = smem_b + cur;
#pragma unroll
        for (int kk = 0; kk < 2; kk++) {
            uint32_t ah[2][4];
            ldsm_x4(ah[0][0], ah[0][1], ah[0][2], ah[0][3],
                    sstage + A_OFF + a_base + kk * 32);
            ldsm_x4(ah[1][0], ah[1][1], ah[1][2], ah[1][3],
                    sstage + A_OFF + a_base + 1280 + kk * 32);
#pragma unroll
            for (int p = 0; p < 3; p++) {
                uint32_t bb[4];
                ldsm_x4(bb[0], bb[1], bb[2], bb[3],
                        sstage + B_OFF + b_base + p * 1280 + kk * 32);
                mma_f16(acc[0][2 * p],     ah[0], &bb[0]);
                mma_f16(acc[1][2 * p],     ah[1], &bb[0]);
                mma_f16(acc[0][2 * p + 1], ah[0], &bb[2]);
                mma_f16(acc[1][2 * p + 1], ah[1], &bb[2]);
            }
        }

        if (c + 1 < 16)
            qkv_cvt_a(smem + ((c + 1) & 1) * STAGE_B, a_r, a_q, av);
    }

    const float qs = 0.125f * LOG2E;
#pragma unroll
    for (int mt = 0; mt < 2; mt++) {
        int r = row0 + warp_m * 32 + mt * 16 + gid;
#pragma unroll
        for (int nt = 0; nt < 6; nt++) {
            int n = warp_n * 48 + nt * 8 + tig * 2;
            if (n < 128) {
                __half* dst = (n < 64) ? g_Q : g_K;
                float s = (n < 64) ? qs : 1.0f;
                int h = n & 63;
                *reinterpret_cast<uint32_t*>(&dst[(size_t)r * HEAD + h]) =
                    f2h2(acc[mt][nt][0] * s, acc[mt][nt][1] * s);
                *reinterpret_cast<uint32_t*>(&dst[(size_t)(r + 8) * HEAD + h]) =
                    f2h2(acc[mt][nt][2] * s, acc[mt][nt][3] * s);
            } else {
                int h = n - 128;
                int b0 = r >> 8, t0 = r & 255;
                int b1 = (r + 8) >> 8, t1 = (r + 8) & 255;
                g_Vt[((size_t)b0 * HEAD + h)     * SEQ + t0] = __float2half_rn(acc[mt][nt][0]);
                g_Vt[((size_t)b0 * HEAD + h + 1) * SEQ + t0] = __float2half_rn(acc[mt][nt][1]);
                g_Vt[((size_t)b1 * HEAD + h)     * SEQ + t1] = __float2half_rn(acc[mt][nt][2]);
                g_Vt[((size_t)b1 * HEAD + h + 1) * SEQ + t1] = __float2half_rn(acc[mt][nt][3]);
            }
        }
    }
}

// ---------------------------------------------------------------------------
// Kernel 2: causal flash attention, fp16 m16n8k16.
// 128 q-rows/block, per-warp causal skip, P in registers.
// NEW: double-buffered cp.async K/V tiles (1 barrier per tile, loads hidden);
//      row-sums l via a constant ones-column MMA (no l bookkeeping);
//      ex2.approx.f32 asm for all exps.
// ---------------------------------------------------------------------------
__global__ void __launch_bounds__(256, 2)
attn_kernel(float* __restrict__ out) {
    __shared__ uint32_t Ks[2][64][36];  // K tile: [key][h-pair]
    __shared__ uint32_t Vs[2][64][36];  // V^T tile: [h][key-pair]

    const int b = blockIdx.y;
    const int qt2 = 1 - blockIdx.x;      // heavy half (4 j-tiles) first
    const int tid = threadIdx.x;
    const int lane = tid & 31;
    const int w = tid >> 5;              // warp 0..7 -> q rows qt2*128 + w*16
    const int gid = lane >> 2;
    const int tig = lane & 3;
    const int jmax_w = 2 * qt2 + (w >> 2);   // last j-tile this warp computes
    const int jend = 2 * qt2 + 1;            // block's last j-tile

    const uint32_t ks_b = smem_u32(Ks);
    const uint32_t vs_b = smem_u32(Vs);
    // ones-column B fragment for the l-accumulator MMA (n=64 column = 1.0)
    const uint32_t ones_bf = (gid == 0) ? 0x3C003C00u : 0u;

    // Q fragments: 4 k16-steps x 4 regs (half2); Q pre-scaled by 0.125*log2e
    uint32_t qf[4][4];
    {
        const size_t qbase = ((size_t)b * SEQ + (size_t)qt2 * 128 + w * 16) * HEAD;
#pragma unroll
        for (int kk = 0; kk < 4; kk++) {
            int h = kk * 16 + tig * 2;
            qf[kk][0] = *reinterpret_cast<const uint32_t*>(&g_Q[qbase + gid * HEAD + h]);
            qf[kk][1] = *reinterpret_cast<const uint32_t*>(&g_Q[qbase + (gid + 8) * HEAD + h]);
            qf[kk][2] = *reinterpret_cast<const uint32_t*>(&g_Q[qbase + gid * HEAD + h + 8]);
            qf[kk][3] = *reinterpret_cast<const uint32_t*>(&g_Q[qbase + (gid + 8) * HEAD + h + 8]);
        }
    }

    float m0 = -1e30f, m1 = -1e30f;
    float o[9][4];   // o[0..7] = output cols; o[8] = row-sum l (ones column)
#pragma unroll
    for (int nt = 0; nt < 9; nt++)
#pragma unroll
        for (int i = 0; i < 4; i++) o[nt][i] = 0.f;

    // ---- prologue: async-load tile 0 ----
    {
#pragma unroll
        for (int s = 0; s < 2; s++) {
            int idx4 = s * 256 + tid;
            int r8 = idx4 >> 3, q8 = idx4 & 7;
            cp16(ks_b + r8 * 144 + q8 * 16,
                 &g_K[((size_t)b * SEQ + r8) * HEAD + q8 * 8]);
            cp16(vs_b + r8 * 144 + q8 * 16,
                 &g_Vt[((size_t)b * HEAD + r8) * SEQ + q8 * 8]);
        }
        asm volatile("cp.async.commit_group;" ::: "memory");
    }

    for (int j = 0; j <= jend; j++) {
        const int buf = j & 1;
        asm volatile("cp.async.wait_group 0;" ::: "memory");
        __syncthreads();   // tile j visible to all; tile j-1 compute complete

        if (j < jend) {    // async-load tile j+1 into the other buffer
            const int nb = (j + 1) & 1;
#pragma unroll
            for (int s = 0; s < 2; s++) {
                int idx4 = s * 256 + tid;
                int r8 = idx4 >> 3, q8 = idx4 & 7;
                cp16(ks_b + nb * 9216 + r8 * 144 + q8 * 16,
                     &g_K[((size_t)b * SEQ + (j + 1) * 64 + r8) * HEAD + q8 * 8]);
                cp16(vs_b + nb * 9216 + r8 * 144 + q8 * 16,
                     &g_Vt[((size_t)b * HEAD + r8) * SEQ + (j + 1) * 64 + q8 * 8]);
            }
            asm volatile("cp.async.commit_group;" ::: "memory");
        }

        if (j > jmax_w) continue;   // causally empty for this warp

        // ---- S = Q @ K^T : 16x64 (32 HMMA) ----
        float sc[8][4];
#pragma unroll
        for (int nt = 0; nt < 8; nt++)
#pragma unroll
            for (int i = 0; i < 4; i++) sc[nt][i] = 0.f;

#pragma unroll
        for (int kk = 0; kk < 4; kk++) {
#pragma unroll
            for (int nt = 0; nt < 8; nt++) {
                uint32_t bf[2];
                bf[0] = Ks[buf][nt * 8 + gid][kk * 8 + tig];
                bf[1] = Ks[buf][nt * 8 + gid][kk * 8 + tig + 4];
                mma_f16(sc[nt], qf[kk], bf);
            }
        }

        // ---- causal mask on this warp's diagonal tile ----
        if (j == jmax_w) {
            int q0 = (w & 3) * 16 + gid, q1 = q0 + 8;
#pragma unroll
            for (int nt = 0; nt < 8; nt++) {
                int kc = nt * 8 + tig * 2;
                if (kc > q0) sc[nt][0] = -1e30f;
                if (kc + 1 > q0) sc[nt][1] = -1e30f;
                if (kc > q1) sc[nt][2] = -1e30f;
                if (kc + 1 > q1) sc[nt][3] = -1e30f;
            }
        }

        // ---- online softmax (log2 domain; l handled by ones-column MMA) ----
        float rm0 = -1e30f, rm1 = -1e30f;
#pragma unroll
        for (int nt = 0; nt < 8; nt++) {
            rm0 = fmaxf(rm0, fmaxf(sc[nt][0], sc[nt][1]));
            rm1 = fmaxf(rm1, fmaxf(sc[nt][2], sc[nt][3]));
        }
        rm0 = fmaxf(rm0, __shfl_xor_sync(0xffffffffu, rm0, 1));
        rm0 = fmaxf(rm0, __shfl_xor_sync(0xffffffffu, rm0, 2));
        rm1 = fmaxf(rm1, __shfl_xor_sync(0xffffffffu, rm1, 1));
        rm1 = fmaxf(rm1, __shfl_xor_sync(0xffffffffu, rm1, 2));

        float mn0 = fmaxf(m0, rm0), mn1 = fmaxf(m1, rm1);
        float a0 = ex2(m0 - mn0), a1 = ex2(m1 - mn1);
        m0 = mn0; m1 = mn1;

#pragma unroll
        for (int nt = 0; nt < 8; nt++) {
            sc[nt][0] = ex2(sc[nt][0] - mn0);
            sc[nt][1] = ex2(sc[nt][1] - mn0);
            sc[nt][2] = ex2(sc[nt][2] - mn1);
            sc[nt][3] = ex2(sc[nt][3] - mn1);
        }

#pragma unroll
        for (int nt = 0; nt < 9; nt++) {
            o[nt][0] *= a0; o[nt][1] *= a0;
            o[nt][2] *= a1; o[nt][3] *= a1;
        }

        // ---- O += P @ V, l += P @ 1 : P stays in registers ----
#pragma unroll
        for (int kk = 0; kk < 4; kk++) {
            uint32_t af[4];
            af[0] = f2h2(sc[2 * kk][0],     sc[2 * kk][1]);
            af[1] = f2h2(sc[2 * kk][2],     sc[2 * kk][3]);
            af[2] = f2h2(sc[2 * kk + 1][0], sc[2 * kk + 1][1]);
            af[3] = f2h2(sc[2 * kk + 1][2], sc[2 * kk + 1][3]);
#pragma unroll
            for (int nt = 0; nt < 8; nt++) {
                uint32_t bf[2];
                bf[0] = Vs[buf][nt * 8 + gid][kk * 8 + tig];
                bf[1] = Vs[buf][nt * 8 + gid][kk * 8 + tig + 4];
                mma_f16(o[nt], af, bf);
            }
            uint32_t of[2] = {ones_bf, ones_bf};
            mma_f16(o[8], af, of);
        }
    }

    // ---- normalize and write out; l lives in o[8][0]/o[8][2] of tig==0 ----
    float l0 = __shfl_sync(0xffffffffu, o[8][0], lane & 28);
    float l1 = __shfl_sync(0xffffffffu, o[8][2], lane & 28);
    float inv0 = 1.f / l0, inv1 = 1.f / l1;
    const size_t ob = ((size_t)b * SEQ + (size_t)qt2 * 128 + w * 16) * HEAD;
#pragma unroll
    for (int nt = 0; nt < 8; nt++) {
        int h = nt * 8 + tig * 2;
        *reinterpret_cast<float2*>(&out[ob + gid * HEAD + h]) =
            make_float2(o[nt][0] * inv0, o[nt][1] * inv0);
        *reinterpret_cast<float2*>(&out[ob + (gid + 8) * HEAD + h]) =
            make_float2(o[nt][2] * inv1, o[nt][3] * inv1);
    }
}

extern "C" void kernel_launch(void* const* d_in, const int* in_sizes, int n_in,
                              void* d_out, int out_size) {
    (void)in_sizes; (void)n_in; (void)out_size;
    const float* x = (const float*)d_in[0];
    const float* Wq = (const float*)d_in[1];
    const float* Wk = (const float*)d_in[2];
    const float* Wv = (const float*)d_in[3];
    float* out = (float*)d_out;

    cudaFuncSetAttribute(qkv_proj_kernel, cudaFuncAttributeMaxDynamicSharedMemorySize,
                         QKV_SMEM);

    wcvt_kernel<<<(192 * 512 + 255) / 256, 256>>>(Wq, Wk, Wv);
    qkv_proj_kernel<<<MROWS / 128, 512, QKV_SMEM>>>(x);
    attn_kernel<<<dim3(2, BATCH), 256>>>(out);
}